// round 3
// baseline (speedup 1.0000x reference)
#include <cuda_runtime.h>

// AUGRU: B=65536 rows, T=50 steps, E=10.
// One thread owns 2 batch rows as one f32x2 pair. Weights duplicated+transposed
// in shared ((w,w) float2), fetched as 16B broadcasts feeding packed
// fma.rn.f32x2. x/attention staged through shared in 2-step chunks with
// coalesced float4 global loads. Buffers reused to keep regs < 255 (no spill).

#define E_   10
#define T_   50
#define BTOT 65536
#define ROWS_PER_CTA 128
#define NPAIR 64          // pairs per CTA = threads per CTA
#define TC   2

typedef unsigned long long u64;

__device__ __forceinline__ u64 pk(float lo, float hi) {
    u64 r; asm("mov.b64 %0, {%1,%2};" : "=l"(r) : "f"(lo), "f"(hi)); return r;
}
__device__ __forceinline__ void upk(u64 v, float& lo, float& hi) {
    asm("mov.b64 {%0,%1}, %2;" : "=f"(lo), "=f"(hi) : "l"(v));
}
__device__ __forceinline__ u64 ffma2(u64 a, u64 b, u64 c) {
    u64 d; asm("fma.rn.f32x2 %0, %1, %2, %3;" : "=l"(d) : "l"(a), "l"(b), "l"(c)); return d;
}
__device__ __forceinline__ u64 fmul2(u64 a, u64 b) {
    u64 d; asm("mul.rn.f32x2 %0, %1, %2;" : "=l"(d) : "l"(a), "l"(b)); return d;
}

// sigmoid(v) = 1/(1+exp(-v)); safe at extremes: exp->inf => rcp->0.
__device__ __forceinline__ float sigm(float v) {
    float e = __expf(-v);
    return __fdividef(1.0f, 1.0f + e);
}
// tanh(v) = 1 - 2/(1+exp(2v)); safe at both extremes.
__device__ __forceinline__ float tanh_f(float v) {
    float e = __expf(2.0f * v);
    return 1.0f - __fdividef(2.0f, 1.0f + e);
}

// acc += s @ W ; w is dup-transposed: w[j*10+k] = (W[k][j], W[k][j])
__device__ __forceinline__ void mv(const float2* __restrict__ w,
                                   const u64* s, u64* acc) {
#pragma unroll
    for (int j = 0; j < E_; j++) {
        u64 a = acc[j];
#pragma unroll
        for (int kk = 0; kk < 5; kk++) {
            ulonglong2 ww = *reinterpret_cast<const ulonglong2*>(w + j * 10 + 2 * kk);
            a = ffma2(s[2 * kk],     ww.x, a);
            a = ffma2(s[2 * kk + 1], ww.y, a);
        }
        acc[j] = a;
    }
}

__global__ void __launch_bounds__(64) augru_kernel(
    const float* __restrict__ X, const float* __restrict__ A, const float* __restrict__ H0,
    const float* __restrict__ WiR, const float* __restrict__ biR, const float* __restrict__ WhR,
    const float* __restrict__ WsR, const float* __restrict__ bsR,
    const float* __restrict__ WiZ, const float* __restrict__ biZ, const float* __restrict__ WhZ,
    const float* __restrict__ WsZ, const float* __restrict__ bsZ,
    const float* __restrict__ WiH, const float* __restrict__ biH, const float* __restrict__ WhH,
    const float* __restrict__ WtH, const float* __restrict__ btH,
    float* __restrict__ Out)
{
    __shared__ __align__(16) float2 Wd[9][100];   // dup-transposed weights
    __shared__ __align__(16) float2 Bd[6][E_];    // dup biases
    __shared__ __align__(16) float  xsf[TC][E_][NPAIR][2];
    __shared__ __align__(16) float  asf[TC][E_][NPAIR][2];

    const int tid = threadIdx.x;           // 0..63, owns pair tid (rows 2*tid, 2*tid+1)
    const int rowBase = blockIdx.x * ROWS_PER_CTA;

    // ---- load weights (dup + transpose) and biases into shared ----
    const float* wsrc[9] = {WiR, WhR, WsR, WiZ, WhZ, WsZ, WiH, WhH, WtH};
#pragma unroll
    for (int m = 0; m < 9; m++) {
        for (int idx = tid; idx < 100; idx += 64) {
            int k = idx / 10, j = idx % 10;
            float w = wsrc[m][idx];
            Wd[m][j * 10 + k] = make_float2(w, w);
        }
    }
    const float* bsrc[6] = {biR, bsR, biZ, bsZ, biH, btH};
    if (tid < E_) {
#pragma unroll
        for (int m = 0; m < 6; m++) {
            float b = bsrc[m][tid];
            Bd[m][tid] = make_float2(b, b);
        }
    }

    // init h (broadcast h0)
    u64 h[E_];
#pragma unroll
    for (int e = 0; e < E_; e++) {
        float v = H0[e];
        h[e] = pk(v, v);
    }

    const u64* xs64 = reinterpret_cast<const u64*>(&xsf[0][0][0][0]);
    const u64* as64 = reinterpret_cast<const u64*>(&asf[0][0][0][0]);
    const float4* Xg = reinterpret_cast<const float4*>(X);
    const float4* Ag = reinterpret_cast<const float4*>(A);

#pragma unroll 1
    for (int t0 = 0; t0 < T_; t0 += TC) {
        __syncthreads();
        // ---- stage 2 steps of x,a for 128 rows (coalesced float4) ----
        // per row: 2*10 floats = 5 float4, contiguous. row stride = 125 float4.
        {
            const long cbase = (long)(t0 * E_) / 4;  // integer: t0 even
#pragma unroll
            for (int it = 0; it < 10; ++it) {
                int idx = it * 64 + tid;       // 0..639
                int r = idx / 5, v = idx % 5;
                long g = (long)(rowBase + r) * 125 + cbase + v;
                float4 dx = Xg[g];
                float4 da = Ag[g];
                int p = r >> 1, hhalf = r & 1;
#pragma unroll
                for (int c = 0; c < 4; c++) {
                    int q = v * 4 + c;
                    int tl = (q >= 10) ? 1 : 0;
                    int e = q - 10 * tl;
                    float fx = (c == 0) ? dx.x : (c == 1) ? dx.y : (c == 2) ? dx.z : dx.w;
                    float fa = (c == 0) ? da.x : (c == 1) ? da.y : (c == 2) ? da.z : da.w;
                    xsf[tl][e][p][hhalf] = fx;
                    asf[tl][e][p][hhalf] = fa;
                }
            }
        }
        __syncthreads();

#pragma unroll 1
        for (int tt = 0; tt < TC; ++tt) {
            // load x (packed pair)
            u64 x[E_];
#pragma unroll
            for (int e = 0; e < E_; e++)
                x[e] = xs64[(tt * E_ + e) * NPAIR + tid];

            u64 u[E_], v[E_], r[E_];

            // ---------------- r gate ----------------
#pragma unroll
            for (int j = 0; j < E_; j++)
                u[j] = *reinterpret_cast<const u64*>(&Bd[0][j]);
            mv(Wd[0], x, u);   // x @ Wi_r
            mv(Wd[1], h, u);   // h @ Wh_r
#pragma unroll
            for (int j = 0; j < E_; j++)
                v[j] = *reinterpret_cast<const u64*>(&Bd[1][j]);
            mv(Wd[2], u, v);   // u @ Ws_r
#pragma unroll
            for (int j = 0; j < E_; j++) {
                float a, b;
                upk(v[j], a, b);
                r[j] = pk(sigm(a), sigm(b));
            }

            // ---------------- z gate ----------------
#pragma unroll
            for (int j = 0; j < E_; j++)
                u[j] = *reinterpret_cast<const u64*>(&Bd[2][j]);
            mv(Wd[3], x, u);   // x @ Wi_z
            mv(Wd[4], h, u);   // h @ Wh_z
#pragma unroll
            for (int j = 0; j < E_; j++)
                v[j] = *reinterpret_cast<const u64*>(&Bd[3][j]);
            mv(Wd[5], u, v);   // u @ Ws_z
            // hz = h * sigmoid(v), overwrite u
#pragma unroll
            for (int j = 0; j < E_; j++) {
                float a, b;
                upk(v[j], a, b);
                u[j] = fmul2(h[j], pk(sigm(a), sigm(b)));
            }

            // ---------------- candidate ----------------
#pragma unroll
            for (int j = 0; j < E_; j++)
                v[j] = *reinterpret_cast<const u64*>(&Bd[4][j]);
            mv(Wd[6], x, v);   // x @ Wi_h   (x dead after this)
            mv(Wd[7], u, v);   // (h*z) @ Wh_h
#pragma unroll
            for (int j = 0; j < E_; j++)
                x[j] = *reinterpret_cast<const u64*>(&Bd[5][j]);  // reuse x as result buf
            mv(Wd[8], v, x);   // v @ Wt_h

            // ---------------- h update ----------------
#pragma unroll
            for (int e = 0; e < E_; e++) {
                float ca, cb;
                upk(x[e], ca, cb);
                ca = tanh_f(ca); cb = tanh_f(cb);

                float a0, a1, r0, r1, h0_, h1_;
                upk(as64[(tt * E_ + e) * NPAIR + tid], a0, a1);
                upk(r[e], r0, r1);
                upk(h[e], h0_, h1_);
                float Ra0 = a0 * r0;
                float Ra1 = a1 * r1;
                h0_ += Ra0 * (ca - h0_);
                h1_ += Ra1 * (cb - h1_);
                h[e] = pk(h0_, h1_);
            }
        }
    }

    // ---- store final h: rows 2*tid, 2*tid+1 ----
    const long r0 = (long)rowBase + 2 * tid;
#pragma unroll
    for (int e = 0; e < E_; e++) {
        float a, b;
        upk(h[e], a, b);
        Out[r0 * E_ + e]       = a;
        Out[(r0 + 1) * E_ + e] = b;
    }
}

extern "C" void kernel_launch(void* const* d_in, const int* in_sizes, int n_in,
                              void* d_out, int out_size) {
    const float* X   = (const float*)d_in[0];
    const float* A   = (const float*)d_in[1];
    const float* H0  = (const float*)d_in[2];
    const float* WiR = (const float*)d_in[3];
    const float* biR = (const float*)d_in[4];
    const float* WhR = (const float*)d_in[5];
    const float* WsR = (const float*)d_in[6];
    const float* bsR = (const float*)d_in[7];
    const float* WiZ = (const float*)d_in[8];
    const float* biZ = (const float*)d_in[9];
    const float* WhZ = (const float*)d_in[10];
    const float* WsZ = (const float*)d_in[11];
    const float* bsZ = (const float*)d_in[12];
    const float* WiH = (const float*)d_in[13];
    const float* biH = (const float*)d_in[14];
    const float* WhH = (const float*)d_in[15];
    const float* WtH = (const float*)d_in[16];
    const float* btH = (const float*)d_in[17];
    float* Out = (float*)d_out;

    dim3 grid(BTOT / ROWS_PER_CTA);  // 512
    dim3 block(NPAIR);               // 64
    augru_kernel<<<grid, block>>>(X, A, H0,
                                  WiR, biR, WhR, WsR, bsR,
                                  WiZ, biZ, WhZ, WsZ, bsZ,
                                  WiH, biH, WhH, WtH, btH,
                                  Out);
}

// round 4
// speedup vs baseline: 1.2289x; 1.2289x over previous
#include <cuda_runtime.h>

// AUGRU: B=65536 rows, T=50 steps, E=10.
// Scalar fp32, ONE batch row per thread (avoids the r3 register-spill disaster:
// 255 regs + DRAM 72% from spilled u64-pair arrays). Live set ~50 floats.
// Weights transposed+padded (12/row) in shared, read as float4/float2 broadcasts.
// x/attention staged through shared in 2-step chunks with coalesced float4 loads.

#define E_   10
#define EP   12            // padded row stride for transposed weights
#define T_   50
#define BTOT 65536
#define ROWS_PER_CTA 128
#define NTHR 128
#define TC   2

// sigmoid(v) = 1/(1+exp(-v)); safe at extremes: exp->inf => rcp->0.
__device__ __forceinline__ float sigm(float v) {
    float e = __expf(-v);
    return __fdividef(1.0f, 1.0f + e);
}
// tanh(v) = 1 - 2/(1+exp(2v)); safe at both extremes.
__device__ __forceinline__ float tanh_f(float v) {
    float e = __expf(2.0f * v);
    return 1.0f - __fdividef(2.0f, 1.0f + e);
}

// acc[j] += sum_k s[k] * w[j*EP+k];  w transposed: w[j*EP+k] = W[k][j]
__device__ __forceinline__ void mv(const float* __restrict__ w,
                                   const float* s, float* acc) {
#pragma unroll
    for (int j = 0; j < E_; j++) {
        const float4* wr = reinterpret_cast<const float4*>(w + j * EP);
        float4 w0 = wr[0];
        float4 w1 = wr[1];
        float2 w2 = reinterpret_cast<const float2*>(w + j * EP)[4];
        float a = acc[j];
        a += s[0] * w0.x; a += s[1] * w0.y; a += s[2] * w0.z; a += s[3] * w0.w;
        a += s[4] * w1.x; a += s[5] * w1.y; a += s[6] * w1.z; a += s[7] * w1.w;
        a += s[8] * w2.x; a += s[9] * w2.y;
        acc[j] = a;
    }
}

__global__ void __launch_bounds__(NTHR) augru_kernel(
    const float* __restrict__ X, const float* __restrict__ A, const float* __restrict__ H0,
    const float* __restrict__ WiR, const float* __restrict__ biR, const float* __restrict__ WhR,
    const float* __restrict__ WsR, const float* __restrict__ bsR,
    const float* __restrict__ WiZ, const float* __restrict__ biZ, const float* __restrict__ WhZ,
    const float* __restrict__ WsZ, const float* __restrict__ bsZ,
    const float* __restrict__ WiH, const float* __restrict__ biH, const float* __restrict__ WhH,
    const float* __restrict__ WtH, const float* __restrict__ btH,
    float* __restrict__ Out)
{
    __shared__ __align__(16) float Wd[9][E_ * EP];    // transposed, padded
    __shared__ __align__(16) float Bd[6][E_];
    __shared__ __align__(16) float xsf[TC][E_][ROWS_PER_CTA];
    __shared__ __align__(16) float asf[TC][E_][ROWS_PER_CTA];

    const int tid = threadIdx.x;           // 0..127, owns row rowBase+tid
    const int rowBase = blockIdx.x * ROWS_PER_CTA;

    // ---- load weights (transpose + pad) and biases into shared ----
    const float* wsrc[9] = {WiR, WhR, WsR, WiZ, WhZ, WsZ, WiH, WhH, WtH};
#pragma unroll
    for (int m = 0; m < 9; m++) {
        if (tid < 120) {
            int j = tid / EP, k = tid % EP;      // j: 0..9 output, k: 0..11
            Wd[m][j * EP + k] = (k < E_) ? wsrc[m][k * E_ + j] : 0.0f;
        }
    }
    const float* bsrc[6] = {biR, bsR, biZ, bsZ, biH, btH};
    if (tid < E_) {
#pragma unroll
        for (int m = 0; m < 6; m++)
            Bd[m][tid] = bsrc[m][tid];
    }

    // init h (broadcast h0)
    float h[E_];
#pragma unroll
    for (int e = 0; e < E_; e++)
        h[e] = H0[e];

    const float4* Xg = reinterpret_cast<const float4*>(X);
    const float4* Ag = reinterpret_cast<const float4*>(A);

#pragma unroll 1
    for (int t0 = 0; t0 < T_; t0 += TC) {
        __syncthreads();
        // ---- stage 2 steps of x,a for 128 rows (coalesced float4) ----
        // per row: 2*10 floats = 5 float4, contiguous. row stride = 125 float4.
        {
            const long cbase = (long)(t0 * E_) / 4;  // exact: t0 even
#pragma unroll
            for (int it = 0; it < 5; ++it) {
                int idx = it * NTHR + tid;           // 0..639
                int r = idx / 5, v = idx % 5;
                long g = (long)(rowBase + r) * 125 + cbase + v;
                float4 dx = Xg[g];
                float4 da = Ag[g];
#pragma unroll
                for (int c = 0; c < 4; c++) {
                    int q = v * 4 + c;
                    int tl = (q >= E_) ? 1 : 0;
                    int e = q - E_ * tl;
                    float fx = (c == 0) ? dx.x : (c == 1) ? dx.y : (c == 2) ? dx.z : dx.w;
                    float fa = (c == 0) ? da.x : (c == 1) ? da.y : (c == 2) ? da.z : da.w;
                    xsf[tl][e][r] = fx;
                    asf[tl][e][r] = fa;
                }
            }
        }
        __syncthreads();

#pragma unroll 1
        for (int tt = 0; tt < TC; ++tt) {
            float x[E_];
#pragma unroll
            for (int e = 0; e < E_; e++)
                x[e] = xsf[tt][e][tid];

            float u[E_], v[E_], r[E_];

            // ---------------- r gate ----------------
#pragma unroll
            for (int j = 0; j < E_; j++) u[j] = Bd[0][j];
            mv(Wd[0], x, u);   // x @ Wi_r
            mv(Wd[1], h, u);   // h @ Wh_r
#pragma unroll
            for (int j = 0; j < E_; j++) v[j] = Bd[1][j];
            mv(Wd[2], u, v);   // u @ Ws_r
#pragma unroll
            for (int j = 0; j < E_; j++) r[j] = sigm(v[j]);

            // ---------------- z gate ----------------
#pragma unroll
            for (int j = 0; j < E_; j++) u[j] = Bd[2][j];
            mv(Wd[3], x, u);   // x @ Wi_z
            mv(Wd[4], h, u);   // h @ Wh_z
#pragma unroll
            for (int j = 0; j < E_; j++) v[j] = Bd[3][j];
            mv(Wd[5], u, v);   // u @ Ws_z
            // hz = h * sigmoid(v), overwrite u
#pragma unroll
            for (int j = 0; j < E_; j++) u[j] = h[j] * sigm(v[j]);

            // ---------------- candidate ----------------
#pragma unroll
            for (int j = 0; j < E_; j++) v[j] = Bd[4][j];
            mv(Wd[6], x, v);   // x @ Wi_h    (x dead after this)
            mv(Wd[7], u, v);   // (h*z) @ Wh_h
#pragma unroll
            for (int j = 0; j < E_; j++) x[j] = Bd[5][j];  // reuse x as result buf
            mv(Wd[8], v, x);   // v @ Wt_h

            // ---------------- h update ----------------
#pragma unroll
            for (int e = 0; e < E_; e++) {
                float c  = tanh_f(x[e]);
                float Ra = asf[tt][e][tid] * r[e];
                h[e] += Ra * (c - h[e]);
            }
        }
    }

    // ---- store final h ----
    const long r0 = (long)(rowBase + tid) * E_;
#pragma unroll
    for (int e = 0; e < E_; e++)
        Out[r0 + e] = h[e];
}

extern "C" void kernel_launch(void* const* d_in, const int* in_sizes, int n_in,
                              void* d_out, int out_size) {
    const float* X   = (const float*)d_in[0];
    const float* A   = (const float*)d_in[1];
    const float* H0  = (const float*)d_in[2];
    const float* WiR = (const float*)d_in[3];
    const float* biR = (const float*)d_in[4];
    const float* WhR = (const float*)d_in[5];
    const float* WsR = (const float*)d_in[6];
    const float* bsR = (const float*)d_in[7];
    const float* WiZ = (const float*)d_in[8];
    const float* biZ = (const float*)d_in[9];
    const float* WhZ = (const float*)d_in[10];
    const float* WsZ = (const float*)d_in[11];
    const float* bsZ = (const float*)d_in[12];
    const float* WiH = (const float*)d_in[13];
    const float* biH = (const float*)d_in[14];
    const float* WhH = (const float*)d_in[15];
    const float* WtH = (const float*)d_in[16];
    const float* btH = (const float*)d_in[17];
    float* Out = (float*)d_out;

    dim3 grid(BTOT / ROWS_PER_CTA);  // 512
    dim3 block(NTHR);                // 128
    augru_kernel<<<grid, block>>>(X, A, H0,
                                  WiR, biR, WhR, WsR, bsR,
                                  WiZ, biZ, WhZ, WsZ, bsZ,
                                  WiH, biH, WhH, WtH, btH,
                                  Out);
}

// round 5
// speedup vs baseline: 12.4691x; 10.1468x over previous
#include <cuda_runtime.h>

// AUGRU: B=65536, T=50, E=10.
// Key fixes vs r4 (which was register-spill bound: regs=255, DRAM 32%, fma 3.8%):
//  1) Algebraic fusion: (x@Wi+bi+h@Wh)@Ws+bs == x@(Wi@Ws) + h@(Wh@Ws) + (bi@Ws+bs)
//     -> 6 matmuls/step instead of 9, no u/v intermediates. Fused weights
//     precomputed once per launch by prep_kernel into __device__ globals.
//  2) __syncwarp() fences every half-mv bound ptxas's shared-load batching window.
//  3) __launch_bounds__(128,4): 128-reg cap, 4 CTAs/SM -> whole grid (512) in one wave.

#define E_   10
#define EP   12            // padded row stride for transposed weights
#define T_   50
#define BTOT 65536
#define ROWS_PER_CTA 128
#define NTHR 128
#define TC   2

// Fused weights, transposed+padded: gW[m][j*EP+k] = W'[k][j].
// m: 0=Wi_r', 1=Wh_r', 2=Wi_z', 3=Wh_z', 4=Wi_h', 5=Wh_h'
__device__ float gW[6][E_ * EP];
// Fused biases: 0=r, 1=z, 2=h
__device__ float gB[3][E_];

__global__ void prep_kernel(
    const float* __restrict__ WiR, const float* __restrict__ biR, const float* __restrict__ WhR,
    const float* __restrict__ WsR, const float* __restrict__ bsR,
    const float* __restrict__ WiZ, const float* __restrict__ biZ, const float* __restrict__ WhZ,
    const float* __restrict__ WsZ, const float* __restrict__ bsZ,
    const float* __restrict__ WiH, const float* __restrict__ biH, const float* __restrict__ WhH,
    const float* __restrict__ WtH, const float* __restrict__ btH)
{
    const int t = threadIdx.x;
    const float* Am[6] = {WiR, WhR, WiZ, WhZ, WiH, WhH};
    const float* Bm[6] = {WsR, WsR, WsZ, WsZ, WtH, WtH};
    if (t < 120) {
        int j = t / EP;   // 0..9  (output col of fused W')
        int k = t % EP;   // 0..11 (input row; 10,11 are padding)
#pragma unroll
        for (int m = 0; m < 6; m++) {
            float s = 0.0f;
            if (k < E_) {
#pragma unroll
                for (int l = 0; l < E_; l++)
                    s = fmaf(Am[m][k * E_ + l], Bm[m][l * E_ + j], s);
            }
            gW[m][j * EP + k] = s;   // transposed store
        }
    }
    const float* bi[3] = {biR, biZ, biH};
    const float* bs[3] = {bsR, bsZ, btH};
    const float* Wo[3] = {WsR, WsZ, WtH};
    if (t < E_) {
#pragma unroll
        for (int m = 0; m < 3; m++) {
            float s = bs[m][t];
#pragma unroll
            for (int l = 0; l < E_; l++)
                s = fmaf(bi[m][l], Wo[m][l * E_ + t], s);
            gB[m][t] = s;
        }
    }
}

// sigmoid(v) = 1/(1+exp(-v)); safe at extremes.
__device__ __forceinline__ float sigm(float v) {
    float e = __expf(-v);
    return __fdividef(1.0f, 1.0f + e);
}
// tanh(v) = 1 - 2/(1+exp(2v)); safe at both extremes.
__device__ __forceinline__ float tanh_f(float v) {
    float e = __expf(2.0f * v);
    return 1.0f - __fdividef(2.0f, 1.0f + e);
}

// acc[j] += dot(s, W'[:,j]); w transposed: w[j*EP+k] = W'[k][j].
// __syncwarp() every 5 rows bounds ptxas's LDS batching window (anti-spill).
__device__ __forceinline__ void mv(const float* __restrict__ w,
                                   const float* s, float* acc) {
#pragma unroll
    for (int j = 0; j < E_; j++) {
        const float4* wr = reinterpret_cast<const float4*>(w + j * EP);
        float4 w0 = wr[0];
        float4 w1 = wr[1];
        float2 w2 = reinterpret_cast<const float2*>(w + j * EP)[4];
        float a = acc[j];
        a = fmaf(s[0], w0.x, a); a = fmaf(s[1], w0.y, a);
        a = fmaf(s[2], w0.z, a); a = fmaf(s[3], w0.w, a);
        a = fmaf(s[4], w1.x, a); a = fmaf(s[5], w1.y, a);
        a = fmaf(s[6], w1.z, a); a = fmaf(s[7], w1.w, a);
        a = fmaf(s[8], w2.x, a); a = fmaf(s[9], w2.y, a);
        acc[j] = a;
        if (j == 4) __syncwarp();
    }
    __syncwarp();
}

__global__ void __launch_bounds__(NTHR, 4) augru_kernel(
    const float* __restrict__ X, const float* __restrict__ A,
    const float* __restrict__ H0, float* __restrict__ Out)
{
    __shared__ __align__(16) float Wd[6][E_ * EP];
    __shared__ __align__(16) float Bs[3][E_];
    __shared__ __align__(16) float xsf[TC][E_][ROWS_PER_CTA];
    __shared__ __align__(16) float asf[TC][E_][ROWS_PER_CTA];

    const int tid = threadIdx.x;           // owns row rowBase+tid
    const int rowBase = blockIdx.x * ROWS_PER_CTA;

    // ---- copy fused weights/biases into shared ----
    for (int i = tid; i < 6 * E_ * EP; i += NTHR)
        (&Wd[0][0])[i] = (&gW[0][0])[i];
    if (tid < 3 * E_)
        (&Bs[0][0])[tid] = (&gB[0][0])[tid];

    // init h (broadcast h0)
    float h[E_];
#pragma unroll
    for (int e = 0; e < E_; e++)
        h[e] = H0[e];

    const float4* Xg = reinterpret_cast<const float4*>(X);
    const float4* Ag = reinterpret_cast<const float4*>(A);

#pragma unroll 1
    for (int t0 = 0; t0 < T_; t0 += TC) {
        __syncthreads();
        // ---- stage 2 steps of x,a for 128 rows (coalesced float4) ----
        {
            const long cbase = (long)(t0 * E_) / 4;  // exact: t0 even
#pragma unroll
            for (int it = 0; it < 5; ++it) {
                int idx = it * NTHR + tid;           // 0..639
                int r = idx / 5, v = idx % 5;
                long g = (long)(rowBase + r) * 125 + cbase + v;
                float4 dx = Xg[g];
                float4 da = Ag[g];
#pragma unroll
                for (int c = 0; c < 4; c++) {
                    int q = v * 4 + c;
                    int tl = (q >= E_) ? 1 : 0;
                    int e = q - E_ * tl;
                    float fx = (c == 0) ? dx.x : (c == 1) ? dx.y : (c == 2) ? dx.z : dx.w;
                    float fa = (c == 0) ? da.x : (c == 1) ? da.y : (c == 2) ? da.z : da.w;
                    xsf[tl][e][r] = fx;
                    asf[tl][e][r] = fa;
                }
            }
        }
        __syncthreads();

#pragma unroll 1
        for (int tt = 0; tt < TC; ++tt) {
            float x[E_];
#pragma unroll
            for (int e = 0; e < E_; e++)
                x[e] = xsf[tt][e][tid];

            float acc[E_], r[E_], hz[E_];

            // ---------------- z gate (fused) ----------------
#pragma unroll
            for (int j = 0; j < E_; j++) acc[j] = Bs[1][j];
            mv(Wd[2], x, acc);
            mv(Wd[3], h, acc);
#pragma unroll
            for (int j = 0; j < E_; j++) hz[j] = h[j] * sigm(acc[j]);

            // ---------------- r gate (fused) ----------------
#pragma unroll
            for (int j = 0; j < E_; j++) acc[j] = Bs[0][j];
            mv(Wd[0], x, acc);
            mv(Wd[1], h, acc);
#pragma unroll
            for (int j = 0; j < E_; j++) r[j] = sigm(acc[j]);

            // ---------------- candidate (fused) ----------------
#pragma unroll
            for (int j = 0; j < E_; j++) acc[j] = Bs[2][j];
            mv(Wd[4], x, acc);    // x dead after this
            mv(Wd[5], hz, acc);   // hz dead after this

            // ---------------- h update ----------------
#pragma unroll
            for (int e = 0; e < E_; e++) {
                float c  = tanh_f(acc[e]);
                float Ra = asf[tt][e][tid] * r[e];
                h[e] += Ra * (c - h[e]);
            }
        }
    }

    // ---- store final h ----
    const long r0 = (long)(rowBase + tid) * E_;
#pragma unroll
    for (int e = 0; e < E_; e++)
        Out[r0 + e] = h[e];
}

extern "C" void kernel_launch(void* const* d_in, const int* in_sizes, int n_in,
                              void* d_out, int out_size) {
    const float* X   = (const float*)d_in[0];
    const float* A   = (const float*)d_in[1];
    const float* H0  = (const float*)d_in[2];
    const float* WiR = (const float*)d_in[3];
    const float* biR = (const float*)d_in[4];
    const float* WhR = (const float*)d_in[5];
    const float* WsR = (const float*)d_in[6];
    const float* bsR = (const float*)d_in[7];
    const float* WiZ = (const float*)d_in[8];
    const float* biZ = (const float*)d_in[9];
    const float* WhZ = (const float*)d_in[10];
    const float* WsZ = (const float*)d_in[11];
    const float* bsZ = (const float*)d_in[12];
    const float* WiH = (const float*)d_in[13];
    const float* biH = (const float*)d_in[14];
    const float* WhH = (const float*)d_in[15];
    const float* WtH = (const float*)d_in[16];
    const float* btH = (const float*)d_in[17];
    float* Out = (float*)d_out;

    prep_kernel<<<1, 128>>>(WiR, biR, WhR, WsR, bsR,
                            WiZ, biZ, WhZ, WsZ, bsZ,
                            WiH, biH, WhH, WtH, btH);

    dim3 grid(BTOT / ROWS_PER_CTA);  // 512
    dim3 block(NTHR);                // 128
    augru_kernel<<<grid, block>>>(X, A, H0, Out);
}

// round 6
// speedup vs baseline: 17.2585x; 1.3841x over previous
#include <cuda_runtime.h>

// AUGRU: B=65536, T=50, E=10.
// r5 was shared-crossbar bound (L1=68.5%): broadcast LDS of weights replicates
// 128B/scalar across the one-per-SM crossbar. Fix: fused weights+biases (2.5KB)
// live in __constant__ memory -> LDC/LDCU on the constant port (static indices
// after full unroll), freeing the L1 crossbar for x/a staging only.
// Pipeline: prep_kernel (fuse Wi@Ws etc.) -> memcpyToSymbolAsync -> main kernel.

#define E_   10
#define T_   50
#define BTOT 65536
#define ROWS_PER_CTA 128
#define NTHR 128
#define TC   2

// Flat fused parameter block:
//  [m*100 + j*10 + k] = W'_m[k][j]  (transposed), m: 0=Wi_r,1=Wh_r,2=Wi_z,3=Wh_z,4=Wi_h,5=Wh_h
//  [600 + m*10 + j]   = fused bias, m: 0=r,1=z,2=h
#define PSZ (6 * 100 + 3 * E_)
__device__   float gAll[PSZ];
__constant__ float cAll[PSZ];

__global__ void prep_kernel(
    const float* __restrict__ WiR, const float* __restrict__ biR, const float* __restrict__ WhR,
    const float* __restrict__ WsR, const float* __restrict__ bsR,
    const float* __restrict__ WiZ, const float* __restrict__ biZ, const float* __restrict__ WhZ,
    const float* __restrict__ WsZ, const float* __restrict__ bsZ,
    const float* __restrict__ WiH, const float* __restrict__ biH, const float* __restrict__ WhH,
    const float* __restrict__ WtH, const float* __restrict__ btH)
{
    const int t = threadIdx.x;
    const float* Am[6] = {WiR, WhR, WiZ, WhZ, WiH, WhH};
    const float* Bm[6] = {WsR, WsR, WsZ, WsZ, WtH, WtH};
    if (t < 100) {
        int j = t / E_;   // output col of fused W'
        int k = t % E_;   // input row
#pragma unroll
        for (int m = 0; m < 6; m++) {
            float s = 0.0f;
#pragma unroll
            for (int l = 0; l < E_; l++)
                s = fmaf(Am[m][k * E_ + l], Bm[m][l * E_ + j], s);
            gAll[m * 100 + j * E_ + k] = s;   // transposed store
        }
    }
    const float* bi[3] = {biR, biZ, biH};
    const float* bs[3] = {bsR, bsZ, btH};
    const float* Wo[3] = {WsR, WsZ, WtH};
    if (t < E_) {
#pragma unroll
        for (int m = 0; m < 3; m++) {
            float s = bs[m][t];
#pragma unroll
            for (int l = 0; l < E_; l++)
                s = fmaf(bi[m][l], Wo[m][l * E_ + t], s);
            gAll[600 + m * E_ + t] = s;
        }
    }
}

// sigmoid(v) = 1/(1+exp(-v)); safe at extremes.
__device__ __forceinline__ float sigm(float v) {
    float e = __expf(-v);
    return __fdividef(1.0f, 1.0f + e);
}
// tanh(v) = 1 - 2/(1+exp(2v)); safe at both extremes.
__device__ __forceinline__ float tanh_f(float v) {
    float e = __expf(2.0f * v);
    return 1.0f - __fdividef(2.0f, 1.0f + e);
}

// acc[j] += dot(s, W'[:,j]) with W' in __constant__ at literal offsets.
template <int OFF>
__device__ __forceinline__ void mvc(const float* s, float* acc) {
#pragma unroll
    for (int j = 0; j < E_; j++) {
        float a = acc[j];
#pragma unroll
        for (int k = 0; k < E_; k++)
            a = fmaf(s[k], cAll[OFF + j * E_ + k], a);
        acc[j] = a;
    }
    __syncwarp();   // bound compiler's load-batching window (anti-spill)
}

__global__ void __launch_bounds__(NTHR, 4) augru_kernel(
    const float* __restrict__ X, const float* __restrict__ A,
    const float* __restrict__ H0, float* __restrict__ Out)
{
    __shared__ __align__(16) float xsf[TC][E_][ROWS_PER_CTA];
    __shared__ __align__(16) float asf[TC][E_][ROWS_PER_CTA];

    const int tid = threadIdx.x;           // owns row rowBase+tid
    const int rowBase = blockIdx.x * ROWS_PER_CTA;

    // init h (broadcast h0)
    float h[E_];
#pragma unroll
    for (int e = 0; e < E_; e++)
        h[e] = H0[e];

    const float4* Xg = reinterpret_cast<const float4*>(X);
    const float4* Ag = reinterpret_cast<const float4*>(A);

#pragma unroll 1
    for (int t0 = 0; t0 < T_; t0 += TC) {
        __syncthreads();
        // ---- stage 2 steps of x,a for 128 rows (coalesced float4) ----
        {
            const long cbase = (long)(t0 * E_) / 4;  // exact: t0 even
#pragma unroll
            for (int it = 0; it < 5; ++it) {
                int idx = it * NTHR + tid;           // 0..639
                int r = idx / 5, v = idx % 5;
                long g = (long)(rowBase + r) * 125 + cbase + v;
                float4 dx = Xg[g];
                float4 da = Ag[g];
#pragma unroll
                for (int c = 0; c < 4; c++) {
                    int q = v * 4 + c;
                    int tl = (q >= E_) ? 1 : 0;
                    int e = q - E_ * tl;
                    float fx = (c == 0) ? dx.x : (c == 1) ? dx.y : (c == 2) ? dx.z : dx.w;
                    float fa = (c == 0) ? da.x : (c == 1) ? da.y : (c == 2) ? da.z : da.w;
                    xsf[tl][e][r] = fx;
                    asf[tl][e][r] = fa;
                }
            }
        }
        __syncthreads();

#pragma unroll 1
        for (int tt = 0; tt < TC; ++tt) {
            float x[E_];
#pragma unroll
            for (int e = 0; e < E_; e++)
                x[e] = xsf[tt][e][tid];

            float acc[E_], r[E_], hz[E_];

            // ---------------- z gate (fused) ----------------
#pragma unroll
            for (int j = 0; j < E_; j++) acc[j] = cAll[600 + E_ + j];
            mvc<200>(x, acc);
            mvc<300>(h, acc);
#pragma unroll
            for (int j = 0; j < E_; j++) hz[j] = h[j] * sigm(acc[j]);

            // ---------------- r gate (fused) ----------------
#pragma unroll
            for (int j = 0; j < E_; j++) acc[j] = cAll[600 + j];
            mvc<0>(x, acc);
            mvc<100>(h, acc);
#pragma unroll
            for (int j = 0; j < E_; j++) r[j] = sigm(acc[j]);

            // ---------------- candidate (fused) ----------------
#pragma unroll
            for (int j = 0; j < E_; j++) acc[j] = cAll[600 + 2 * E_ + j];
            mvc<400>(x, acc);    // x dead after this
            mvc<500>(hz, acc);   // hz dead after this

            // ---------------- h update ----------------
#pragma unroll
            for (int e = 0; e < E_; e++) {
                float c  = tanh_f(acc[e]);
                float Ra = asf[tt][e][tid] * r[e];
                h[e] += Ra * (c - h[e]);
            }
        }
    }

    // ---- store final h ----
    const long r0 = (long)(rowBase + tid) * E_;
#pragma unroll
    for (int e = 0; e < E_; e++)
        Out[r0 + e] = h[e];
}

extern "C" void kernel_launch(void* const* d_in, const int* in_sizes, int n_in,
                              void* d_out, int out_size) {
    const float* X   = (const float*)d_in[0];
    const float* A   = (const float*)d_in[1];
    const float* H0  = (const float*)d_in[2];
    const float* WiR = (const float*)d_in[3];
    const float* biR = (const float*)d_in[4];
    const float* WhR = (const float*)d_in[5];
    const float* WsR = (const float*)d_in[6];
    const float* bsR = (const float*)d_in[7];
    const float* WiZ = (const float*)d_in[8];
    const float* biZ = (const float*)d_in[9];
    const float* WhZ = (const float*)d_in[10];
    const float* WsZ = (const float*)d_in[11];
    const float* bsZ = (const float*)d_in[12];
    const float* WiH = (const float*)d_in[13];
    const float* biH = (const float*)d_in[14];
    const float* WhH = (const float*)d_in[15];
    const float* WtH = (const float*)d_in[16];
    const float* btH = (const float*)d_in[17];
    float* Out = (float*)d_out;

    prep_kernel<<<1, 128>>>(WiR, biR, WhR, WsR, bsR,
                            WiZ, biZ, WhZ, WsZ, bsZ,
                            WiH, biH, WhH, WtH, btH);

    // fused params -> constant bank (D2D memcpy, graph-capturable)
    void* gsym = nullptr;
    cudaGetSymbolAddress(&gsym, gAll);
    cudaMemcpyToSymbolAsync(cAll, gsym, PSZ * sizeof(float), 0,
                            cudaMemcpyDeviceToDevice, 0);

    dim3 grid(BTOT / ROWS_PER_CTA);  // 512
    dim3 block(NTHR);                // 128
    augru_kernel<<<grid, block>>>(X, A, H0, Out);
}